// round 8
// baseline (speedup 1.0000x reference)
#include <cuda_runtime.h>
#include <cuda_bf16.h>

// XORNet forward: 2-layer LIF spiking net (snntorch Leaky, subtract reset).
// R6 post-mortem: full lane-repack regressed (issue 77.8->60.6, same pipe%):
// packed ops cut issue slots but not pipe cycles, and halving the number of
// independent chains repaid the savings as latency stalls.
// R7 = R4 dataflow (4 independent lanes, neuron-pair packing) with only two
// changes that do NOT narrow ILP:
//   1. s1/s2 stored as F2 pairs -> reset subtract via ONE fma.rn.f32x2 per
//      pair (was two scalar FFMAs); lane-wise IEEE-RN identical.
//   2. persistent grid (592 blocks = 148 SMs x 4 CTAs, grid-stride loop):
//      kills the 2-wave quantization + wave transition, amortizes weights.
// Rounding chain unchanged: rel_err must remain exactly 8.596e-4.

#define SNN_T 20
#define SNN_H 4

union F2 { float2 f; unsigned long long u; };

__device__ __forceinline__ void mul2(F2& d, const F2& a, const F2& b) {
    asm("mul.rn.f32x2 %0, %1, %2;" : "=l"(d.u) : "l"(a.u), "l"(b.u));
}
__device__ __forceinline__ void add2(F2& d, const F2& a, const F2& b) {
    asm("add.rn.f32x2 %0, %1, %2;" : "=l"(d.u) : "l"(a.u), "l"(b.u));
}
__device__ __forceinline__ void fma2(F2& d, const F2& a, const F2& b, const F2& c) {
    asm("fma.rn.f32x2 %0, %1, %2, %3;" : "=l"(d.u) : "l"(a.u), "l"(b.u), "l"(c.u));
}
// 1.0f if a > b else 0.0f, single SASS FSET
__device__ __forceinline__ float fset_gt(float a, float b) {
    float r;
    asm("set.gt.f32.f32 %0, %1, %2;" : "=f"(r) : "f"(a), "f"(b));
    return r;
}

__global__ __launch_bounds__(256) void xornet_snn_kernel(
    const float* __restrict__ x,    // [B, 2]
    const float* __restrict__ w1,   // [4, 2]
    const float* __restrict__ w2,   // [1, 4]
    float* __restrict__ out,        // [T, B, 1]
    int B)
{
    const int N4 = B >> 2;                       // float4 groups
    const int stride = gridDim.x * blockDim.x;
    const int tid0 = blockIdx.x * blockDim.x + threadIdx.x;

    // Broadcast weights once per thread (L1/L2 hit after first warp).
    float w1r0[SNN_H], w1r1[SNN_H], w2r[SNN_H];
    F2 cn1, c09;
#pragma unroll
    for (int h = 0; h < SNN_H; h++) {
        w1r0[h] = __ldg(&w1[2 * h]);
        w1r1[h] = __ldg(&w1[2 * h + 1]);
        w2r[h]  = __ldg(&w2[h]);
    }
    cn1.f = make_float2(-1.0f, -1.0f);
    c09.f = make_float2(0.9f, 0.9f);

    for (int i = tid0; i < N4; i += stride) {
        // x for 4 batch elements: 2x float4.
        const float4 xa = __ldg(&((const float4*)x)[2 * i]);
        const float4 xb = __ldg(&((const float4*)x)[2 * i + 1]);
        const float x0[4] = {xa.x, xa.z, xb.x, xb.z};
        const float x1[4] = {xa.y, xa.w, xb.y, xb.w};

        // cur[l][p] packs neurons (2p, 2p+1) for batch lane l.
        F2 cur[4][2];
#pragma unroll
        for (int l = 0; l < 4; l++)
#pragma unroll
            for (int p = 0; p < 2; p++) {
                cur[l][p].f.x = fmaf(x1[l], w1r1[2 * p],     __fmul_rn(x0[l], w1r0[2 * p]));
                cur[l][p].f.y = fmaf(x1[l], w1r1[2 * p + 1], __fmul_rn(x0[l], w1r0[2 * p + 1]));
            }

        // State: membranes + spikes packed per neuron-pair; 4 independent lanes.
        F2 m1[4][2], s1[4][2];
        F2 m2p[2], s2p[2];          // layer-2: lanes (0,1) and (2,3)
#pragma unroll
        for (int l = 0; l < 4; l++)
#pragma unroll
            for (int p = 0; p < 2; p++) { m1[l][p].u = 0ull; s1[l][p].u = 0ull; }
        m2p[0].u = 0ull; m2p[1].u = 0ull; s2p[0].u = 0ull; s2p[1].u = 0ull;

        float4* outp = (float4*)out + i;

#pragma unroll
        for (int t = 0; t < SNN_T; t++) {
            float o[4];
#pragma unroll
            for (int l = 0; l < 4; l++) {
#pragma unroll
                for (int p = 0; p < 2; p++) {
                    F2 mm;
                    mul2(mm, m1[l][p], c09);        // 0.9*m      (packed RN)
                    add2(mm, mm, cur[l][p]);        // + cur      (packed RN)
                    fma2(mm, s1[l][p], cn1, mm);    // - reset    (== sub for s in {0,1})
                    m1[l][p] = mm;
                    s1[l][p].f.x = fset_gt(mm.f.x, 1.0f);   // spike = (m > 1)
                    s1[l][p].f.y = fset_gt(mm.f.y, 1.0f);
                }
                // spk1 @ w2^T: binary s -> exact products, k-ascending fma chain.
                float oo = __fmul_rn(s1[l][0].f.x, w2r[0]);
                oo = fmaf(s1[l][0].f.y, w2r[1], oo);
                oo = fmaf(s1[l][1].f.x, w2r[2], oo);
                oo = fmaf(s1[l][1].f.y, w2r[3], oo);
                o[l] = oo;
            }
            // layer-2 LIF, packed across batch-lane pairs
#pragma unroll
            for (int q = 0; q < 2; q++) {
                F2 op; op.f = make_float2(o[2 * q], o[2 * q + 1]);
                F2 mm;
                mul2(mm, m2p[q], c09);
                add2(mm, mm, op);
                fma2(mm, s2p[q], cn1, mm);
                m2p[q] = mm;
                s2p[q].f.x = fset_gt(mm.f.x, 1.0f);
                s2p[q].f.y = fset_gt(mm.f.y, 1.0f);
            }
            float4 ov;
            ov.x = s2p[0].f.x; ov.y = s2p[0].f.y;
            ov.z = s2p[1].f.x; ov.w = s2p[1].f.y;
            *outp = ov;                  // warp-coalesced STG.128
            outp += N4;
        }
    }
}

extern "C" void kernel_launch(void* const* d_in, const int* in_sizes, int n_in,
                              void* d_out, int out_size)
{
    const float* x  = (const float*)d_in[0];   // [B, 2]
    const float* w1 = (const float*)d_in[1];   // [4, 2]
    const float* w2 = (const float*)d_in[2];   // [1, 4]
    float* out = (float*)d_out;                // [T, B, 1]

    const int B = in_sizes[0] / 2;             // 1,048,576
    const int threads = 256;
    const int blocks = 148 * 4;                // persistent: one wave at occ=4

    xornet_snn_kernel<<<blocks, threads>>>(x, w1, w2, out, B);
}

// round 9
// speedup vs baseline: 1.0191x; 1.0191x over previous
#include <cuda_runtime.h>
#include <cuda_bf16.h>

// XORNet forward: 2-layer LIF spiking net (snntorch Leaky, subtract reset).
// History: R4 = 16.86us best (issue 77.8, occ 40.2, regs 64).
//   R6 (full lane repack)           -> 18.6us: halved ILP chains, issue 60.6.
//   R7 (FFMA2 reset + persistent)   -> 18.8us: regs 72 -> occ 32.5, issue 65.
// R8 = R4 verbatim + ONE change: reset subtract via fma.rn.f32x2 (one FFMA2
// replaces two scalar FFMAs per neuron-pair; ~80 -> ~70 issue slots/timestep),
// with __launch_bounds__(256, 4) pinning regs <= 64 so occupancy cannot drop.
// Numerics bit-identical to R4: lane-wise IEEE-RN, same evaluation order
//   m = ((0.9*m) + cur) - s_prev ; s = (m > 1); rel_err canary = 8.596e-4.

#define SNN_T 20
#define SNN_H 4

union F2 { float2 f; unsigned long long u; };

__device__ __forceinline__ void mul2(F2& d, const F2& a, const F2& b) {
    asm("mul.rn.f32x2 %0, %1, %2;" : "=l"(d.u) : "l"(a.u), "l"(b.u));
}
__device__ __forceinline__ void add2(F2& d, const F2& a, const F2& b) {
    asm("add.rn.f32x2 %0, %1, %2;" : "=l"(d.u) : "l"(a.u), "l"(b.u));
}
__device__ __forceinline__ void fma2(F2& d, const F2& a, const F2& b, const F2& c) {
    asm("fma.rn.f32x2 %0, %1, %2, %3;" : "=l"(d.u) : "l"(a.u), "l"(b.u), "l"(c.u));
}
// 1.0f if a > b else 0.0f, single SASS FSET
__device__ __forceinline__ float fset_gt(float a, float b) {
    float r;
    asm("set.gt.f32.f32 %0, %1, %2;" : "=f"(r) : "f"(a), "f"(b));
    return r;
}

__global__ __launch_bounds__(256, 4) void xornet_snn_kernel(
    const float* __restrict__ x,    // [B, 2]
    const float* __restrict__ w1,   // [4, 2]
    const float* __restrict__ w2,   // [1, 4]
    float* __restrict__ out,        // [T, B, 1]
    int B)
{
    const int i = blockIdx.x * blockDim.x + threadIdx.x;  // handles b = 4i..4i+3
    if (i * 4 >= B) return;
    const int Bq = B >> 2;

    // Broadcast weights (L2/L1 hit after first warp).
    float w1r0[SNN_H], w1r1[SNN_H], w2r[SNN_H];
    F2 cn1, c09;
#pragma unroll
    for (int h = 0; h < SNN_H; h++) {
        w1r0[h] = __ldg(&w1[2 * h]);
        w1r1[h] = __ldg(&w1[2 * h + 1]);
        w2r[h]  = __ldg(&w2[h]);
    }
    cn1.f = make_float2(-1.0f, -1.0f);
    c09.f = make_float2(0.9f, 0.9f);

    // x for 4 batch elements: 2x float4.
    const float4 xa = __ldg(&((const float4*)x)[2 * i]);
    const float4 xb = __ldg(&((const float4*)x)[2 * i + 1]);
    const float x0[4] = {xa.x, xa.z, xb.x, xb.z};
    const float x1[4] = {xa.y, xa.w, xb.y, xb.w};

    // cur[l][p] packs neurons (2p, 2p+1) for batch lane l (k-ascending fma dot).
    F2 cur[4][2];
#pragma unroll
    for (int l = 0; l < 4; l++)
#pragma unroll
        for (int p = 0; p < 2; p++) {
            cur[l][p].f.x = fmaf(x1[l], w1r1[2 * p],     __fmul_rn(x0[l], w1r0[2 * p]));
            cur[l][p].f.y = fmaf(x1[l], w1r1[2 * p + 1], __fmul_rn(x0[l], w1r0[2 * p + 1]));
        }

    // State: membranes + spikes packed per neuron-pair; 4 independent lanes.
    F2 m1[4][2], s1[4][2];
    F2 m2p[2], s2p[2];          // layer-2: batch-lane pairs (0,1) and (2,3)
#pragma unroll
    for (int l = 0; l < 4; l++)
#pragma unroll
        for (int p = 0; p < 2; p++) { m1[l][p].u = 0ull; s1[l][p].u = 0ull; }
    m2p[0].u = 0ull; m2p[1].u = 0ull; s2p[0].u = 0ull; s2p[1].u = 0ull;

    float4* outp = (float4*)out + i;

#pragma unroll
    for (int t = 0; t < SNN_T; t++) {
        float o[4];
#pragma unroll
        for (int l = 0; l < 4; l++) {
#pragma unroll
            for (int p = 0; p < 2; p++) {
                F2 mm;
                mul2(mm, m1[l][p], c09);        // 0.9*m      (packed RN)
                add2(mm, mm, cur[l][p]);        // + cur      (packed RN)
                fma2(mm, s1[l][p], cn1, mm);    // - reset    (== sub for s in {0,1})
                m1[l][p] = mm;
                s1[l][p].f.x = fset_gt(mm.f.x, 1.0f);   // spike = (m > 1)
                s1[l][p].f.y = fset_gt(mm.f.y, 1.0f);
            }
            // spk1 @ w2^T: binary s -> exact products, k-ascending fma chain.
            float oo = __fmul_rn(s1[l][0].f.x, w2r[0]);
            oo = fmaf(s1[l][0].f.y, w2r[1], oo);
            oo = fmaf(s1[l][1].f.x, w2r[2], oo);
            oo = fmaf(s1[l][1].f.y, w2r[3], oo);
            o[l] = oo;
        }
        // layer-2 LIF, packed across batch-lane pairs
#pragma unroll
        for (int q = 0; q < 2; q++) {
            F2 op; op.f = make_float2(o[2 * q], o[2 * q + 1]);
            F2 mm;
            mul2(mm, m2p[q], c09);
            add2(mm, mm, op);
            fma2(mm, s2p[q], cn1, mm);
            m2p[q] = mm;
            s2p[q].f.x = fset_gt(mm.f.x, 1.0f);
            s2p[q].f.y = fset_gt(mm.f.y, 1.0f);
        }
        float4 ov;
        ov.x = s2p[0].f.x; ov.y = s2p[0].f.y;
        ov.z = s2p[1].f.x; ov.w = s2p[1].f.y;
        *outp = ov;                  // warp-coalesced STG.128
        outp += Bq;
    }
}

extern "C" void kernel_launch(void* const* d_in, const int* in_sizes, int n_in,
                              void* d_out, int out_size)
{
    const float* x  = (const float*)d_in[0];   // [B, 2]
    const float* w1 = (const float*)d_in[1];   // [4, 2]
    const float* w2 = (const float*)d_in[2];   // [1, 4]
    float* out = (float*)d_out;                // [T, B, 1]

    const int B = in_sizes[0] / 2;             // 1,048,576
    const int threads = 256;
    const int nthreads = B / 4;
    const int blocks = (nthreads + threads - 1) / threads;

    xornet_snn_kernel<<<blocks, threads>>>(x, w1, w2, out, B);
}